// round 7
// baseline (speedup 1.0000x reference)
#include <cuda_runtime.h>

#define B_ 2
#define N_ 1024
#define D_ 128
#define H_ 64

typedef unsigned long long u64;

// Scratch (no allocations allowed): intermediate projections.
__device__ float g_ai[B_ * N_ * H_];    // [b][n][h]
__device__ float g_ajbT[B_ * H_ * N_];  // [b][h][n]  (aj + b1, transposed)

// ---- packed f32x2 helpers (sm_103a; only add/mul/fma exist packed) ----
__device__ __forceinline__ u64 f32x2_add(u64 a, u64 b) {
    u64 d; asm("add.rn.f32x2 %0,%1,%2;" : "=l"(d) : "l"(a), "l"(b)); return d;
}
__device__ __forceinline__ u64 f32x2_fma(u64 a, u64 b, u64 c) {
    u64 d; asm("fma.rn.f32x2 %0,%1,%2,%3;" : "=l"(d) : "l"(a), "l"(b), "l"(c)); return d;
}
__device__ __forceinline__ u64 f32x2_pack(float lo, float hi) {
    u64 d; asm("mov.b64 %0,{%1,%2};" : "=l"(d) : "f"(lo), "f"(hi)); return d;
}
__device__ __forceinline__ void f32x2_unpack(float& lo, float& hi, u64 v) {
    asm("mov.b64 {%0,%1},%2;" : "=f"(lo), "=f"(hi) : "l"(v));
}
// ReLU on a packed pair: mov.b64 pack/unpack are register renames (free);
// cost = 2 scalar FMNMX, which land on the ALU pipe (balances vs fma pipe).
__device__ __forceinline__ u64 f32x2_relu(u64 a) {
    float lo, hi; f32x2_unpack(lo, hi, a);
    return f32x2_pack(fmaxf(lo, 0.f), fmaxf(hi, 0.f));
}

// ---------------------------------------------------------------------------
// Pass 1: ai = E @ Wi^T ; ajbT = (E @ Wj^T + b1) transposed to [h][n].
// Block = 256 threads, 8 rows of E (r = tid>>5 warp-uniform -> Esh read is a
// pure broadcast; ob = (tid&31)*4 -> conflict-free LDS.128 on Wc).
// Grid = 256 -> multi-CTA/SM latency overlap.
// ---------------------------------------------------------------------------
__global__ __launch_bounds__(256) void pass1_kernel(
    const float* __restrict__ E, const float* __restrict__ W1,
    const float* __restrict__ b1)
{
    __shared__ float Esh[8][32];
    __shared__ float Wc[32][132];   // padded: 4-way STS conflicts max, rows 16B-aligned

    const int tid = threadIdx.x;
    const int r = tid >> 5;
    const int ob = (tid & 31) * 4;
    const int row0 = blockIdx.x * 8;

    float acc[4] = {0.f, 0.f, 0.f, 0.f};

    for (int dc = 0; dc < D_; dc += 32) {
        __syncthreads();
        {   // Stage 8x32 chunk of E (coalesced, one elem per thread).
            int rr = tid >> 5, dd = tid & 31;
            Esh[rr][dd] = E[(row0 + rr) * D_ + dc + dd];
        }
        // Stage W chunk, coalesced LDG (consecutive lanes -> consecutive dd).
#pragma unroll
        for (int k = tid; k < 32 * 128; k += 256) {
            int o = k >> 5, dd = k & 31;
            float v = (o < H_) ? W1[o * (2 * D_) + dc + dd]
                               : W1[(o - H_) * (2 * D_) + D_ + dc + dd];
            Wc[dd][o] = v;
        }
        __syncthreads();
#pragma unroll
        for (int dd = 0; dd < 32; dd++) {
            const float e = Esh[r][dd];                     // warp broadcast
            const float4 w4 = *(const float4*)&Wc[dd][ob];  // conflict-free
            acc[0] += e * w4.x;  acc[1] += e * w4.y;
            acc[2] += e * w4.z;  acc[3] += e * w4.w;
        }
    }

    const int row = row0 + r;            // row = b*N + n
    if (ob < H_) {
        *(float4*)&g_ai[row * H_ + ob] = make_float4(acc[0], acc[1], acc[2], acc[3]);
    } else {
        const int b = row >> 10;
        const int n = row & (N_ - 1);
        const int h0 = ob - H_;
#pragma unroll
        for (int k = 0; k < 4; k++)
            g_ajbT[(b * H_ + h0 + k) * N_ + n] = acc[k] + b1[h0 + k];
    }
}

// ---------------------------------------------------------------------------
// Pass 2: fused edge weights + mask + softmax + write.
// Grid = B * N/8 = 256 blocks, 128 threads = 4 warps; warp w owns rows
// i0 = i_base + 2w, i0+1. Inner loop: 4 ADD2 + 8 FMNMX + 4 FFMA2 per
// (h, 8 outputs) vs 24 scalar before. Broadcast operands ((ai,ai) pairs +
// (w2,w2)) pre-packed in SMEM: zero per-iter pack MOVs.
// ---------------------------------------------------------------------------
__global__ __launch_bounds__(128, 4) void pass2_kernel(
    const int* __restrict__ visited,
    const float* __restrict__ W2, const float* __restrict__ b2,
    float* __restrict__ out)
{
    __shared__ float ajb[H_][128];          // 32 KB
    __shared__ u64 aa_sh[4][H_][2];         // 4 KB: [(ai0,ai0),(ai1,ai1)] per (warp,h)
    __shared__ u64 ww_sh[H_];               // 512 B: (w2,w2)
    __shared__ int vis_sh[N_];              // 4 KB

    const int tid = threadIdx.x;
    const int w = tid >> 5, lane = tid & 31;
    const int b = blockIdx.x >> 7;
    const int i_base = (blockIdx.x & 127) * 8;
    const int i0 = i_base + 2 * w;

#pragma unroll
    for (int k = tid; k < 4 * H_; k += 128) {
        int wi = k >> 6, h = k & 63;
        int ii = i_base + 2 * wi;
        float a0v = g_ai[(b * N_ + ii) * H_ + h];
        float a1v = g_ai[(b * N_ + ii + 1) * H_ + h];
        aa_sh[wi][h][0] = f32x2_pack(a0v, a0v);
        aa_sh[wi][h][1] = f32x2_pack(a1v, a1v);
    }
    if (tid < H_) { float wv = W2[tid]; ww_sh[tid] = f32x2_pack(wv, wv); }
#pragma unroll
    for (int k = tid; k < N_; k += 128) vis_sh[k] = visited[b * N_ + k];

    u64 acc0[8][2], acc1[8][2];             // packed pairs: (j+0,j+1),(j+2,j+3)

#pragma unroll
    for (int t = 0; t < 8; t++) {
        __syncthreads();
#pragma unroll
        for (int k = tid; k < H_ * 32; k += 128) {
            int h = k >> 5, c4 = k & 31;
            *(float4*)&ajb[h][c4 * 4] =
                *(const float4*)&g_ajbT[(b * H_ + h) * N_ + t * 128 + c4 * 4];
        }
        __syncthreads();

        u64 s00 = 0, s01 = 0, s10 = 0, s11 = 0;   // 0.0f packed
#pragma unroll 8
        for (int h = 0; h < H_; h++) {
            const ulonglong2 aa = *(const ulonglong2*)&aa_sh[w][h][0]; // LDS.128 bcast
            const u64 ww = ww_sh[h];                                   // LDS.64 bcast
            const ulonglong2 v = *(const ulonglong2*)&ajb[h][lane * 4]; // LDS.128
            s00 = f32x2_fma(f32x2_relu(f32x2_add(aa.x, v.x)), ww, s00);
            s01 = f32x2_fma(f32x2_relu(f32x2_add(aa.x, v.y)), ww, s01);
            s10 = f32x2_fma(f32x2_relu(f32x2_add(aa.y, v.x)), ww, s10);
            s11 = f32x2_fma(f32x2_relu(f32x2_add(aa.y, v.y)), ww, s11);
        }
        acc0[t][0] = s00; acc0[t][1] = s01;
        acc1[t][0] = s10; acc1[t][1] = s11;
    }

    // ---- unpack + mask + softmax for both rows (in registers, warp-wide) ----
    float a0[8][4], a1[8][4];
#pragma unroll
    for (int t = 0; t < 8; t++) {
        f32x2_unpack(a0[t][0], a0[t][1], acc0[t][0]);
        f32x2_unpack(a0[t][2], a0[t][3], acc0[t][1]);
        f32x2_unpack(a1[t][0], a1[t][1], acc1[t][0]);
        f32x2_unpack(a1[t][2], a1[t][3], acc1[t][1]);
    }

    const float bb = b2[0];
    const bool vi0 = vis_sh[i0] != 0;
    const bool vi1 = vis_sh[i0 + 1] != 0;
    float m0 = -3.4e38f, m1 = -3.4e38f;
#pragma unroll
    for (int t = 0; t < 8; t++)
#pragma unroll
        for (int k = 0; k < 4; k++) {
            const int j = t * 128 + lane * 4 + k;
            const bool vj = vis_sh[j] != 0;
            float e0 = (vi0 || vj) ? -1.0e9f : (a0[t][k] + bb);
            float e1 = (vi1 || vj) ? -1.0e9f : (a1[t][k] + bb);
            a0[t][k] = e0; a1[t][k] = e1;
            m0 = fmaxf(m0, e0); m1 = fmaxf(m1, e1);
        }
#pragma unroll
    for (int o = 16; o > 0; o >>= 1) {
        m0 = fmaxf(m0, __shfl_xor_sync(0xffffffffu, m0, o));
        m1 = fmaxf(m1, __shfl_xor_sync(0xffffffffu, m1, o));
    }

    float sum0 = 0.f, sum1 = 0.f;
#pragma unroll
    for (int t = 0; t < 8; t++)
#pragma unroll
        for (int k = 0; k < 4; k++) {
            const float p0 = __expf(a0[t][k] - m0);
            const float p1 = __expf(a1[t][k] - m1);
            a0[t][k] = p0; a1[t][k] = p1;
            sum0 += p0; sum1 += p1;
        }
#pragma unroll
    for (int o = 16; o > 0; o >>= 1) {
        sum0 += __shfl_xor_sync(0xffffffffu, sum0, o);
        sum1 += __shfl_xor_sync(0xffffffffu, sum1, o);
    }

    const float inv0 = 1.f / sum0;
    const float inv1 = 1.f / sum1;
    float* orow0 = out + (size_t)(b * N_ + i0) * N_;
    float* orow1 = orow0 + N_;
#pragma unroll
    for (int t = 0; t < 8; t++) {
        *(float4*)&orow0[t * 128 + lane * 4] =
            make_float4(a0[t][0] * inv0, a0[t][1] * inv0,
                        a0[t][2] * inv0, a0[t][3] * inv0);
        *(float4*)&orow1[t * 128 + lane * 4] =
            make_float4(a1[t][0] * inv1, a1[t][1] * inv1,
                        a1[t][2] * inv1, a1[t][3] * inv1);
    }
}

extern "C" void kernel_launch(void* const* d_in, const int* in_sizes, int n_in,
                              void* d_out, int out_size) {
    const float* E  = (const float*)d_in[0];
    const int* vis  = (const int*)d_in[1];   // jax bool -> int32 in harness
    // d_in[2] = remaining_capacity: unused by the reference.
    const float* W1 = (const float*)d_in[3];
    const float* b1 = (const float*)d_in[4];
    const float* W2 = (const float*)d_in[5];
    const float* b2 = (const float*)d_in[6];
    float* out      = (float*)d_out;

    pass1_kernel<<<256, 256>>>(E, W1, b1);
    pass2_kernel<<<256, 128>>>(vis, W2, b2, out);
}